// round 3
// baseline (speedup 1.0000x reference)
#include <cuda_runtime.h>
#include <math.h>

#define CC 4096
#define NN 1024
#define CN (CC*NN)
#define NEGV (-1e30f)

// ---------------- device scratch (no allocations allowed) ----------------
__device__ float d_D0[NN*NN];          // masked cos0 (vs known)
__device__ float d_D1[NN*NN];          // masked cos1 (vs generated)
__device__ float d_normG[NN];
__device__ float d_normK[NN];
__device__ float d_meanAcc[4];
__device__ float d_topW[2][NN][2];
__device__ int   d_topI[2][NN][2];
__device__ float d_wfin[8];            // [0..3]=weights, [4..7]=weights*dup (row-0 artifact)

typedef unsigned long long u64;

__device__ __forceinline__ u64 pack2(float x, float y) {
    u64 r; asm("mov.b64 %0, {%1,%2};" : "=l"(r) : "f"(x), "f"(y)); return r;
}
__device__ __forceinline__ float2 unpack2(u64 v) {
    float2 r; asm("mov.b64 {%0,%1}, %2;" : "=f"(r.x), "=f"(r.y) : "l"(v)); return r;
}
// Blackwell packed fp32 FMA: 2 FMAs per lane per instruction
__device__ __forceinline__ void fma2(u64 &d, u64 a, u64 b) {
    asm("fma.rn.f32x2 %0, %1, %2, %0;" : "+l"(d) : "l"(a), "l"(b));
}

// ---------------- kernel 0: zero accumulators (must run every replay) ----
__global__ void k_init() {
    int t = blockIdx.x * blockDim.x + threadIdx.x;
    if (t < NN) { d_normG[t] = 0.f; d_normK[t] = 0.f; }
    if (t < 4)  d_meanAcc[t] = 0.f;
}

// ---------------- kernel 1: copy inputs to out[0..2CN) + column norms ----
__global__ void k_copynorm(const float* __restrict__ G, const float* __restrict__ K,
                           float* __restrict__ out) {
    int n  = blockIdx.x * 256 + threadIdx.x;   // column (patch index)
    int c0 = blockIdx.y * 128;                 // channel chunk
    float sg = 0.f, sk = 0.f;
    #pragma unroll 4
    for (int i = 0; i < 128; i++) {
        int idx = (c0 + i) * NN + n;
        float g = G[idx], k = K[idx];
        out[idx]      = g;
        out[CN + idx] = k;
        sg += g * g;
        sk += k * k;
    }
    atomicAdd(&d_normG[n], sg);
    atomicAdd(&d_normK[n], sk);
}

// ---------------- kernel 2: dual fp32 GEMM (FFMA2), cos + mask epilogue --
// A = G (stored [C][N], reduction dim is the slow axis for both operands).
// z=0: B = known -> cos0 ; z=1: B = generated -> cos1.
__global__ __launch_bounds__(256) void k_gemm(const float* __restrict__ G,
                                              const float* __restrict__ K,
                                              const float* __restrict__ flag) {
    __shared__ float As[2][16][128];
    __shared__ float Bs[2][16][128];

    const int z  = blockIdx.z;
    const float* A = G;
    const float* B = z ? G : K;
    const int m0 = blockIdx.y * 128, n0 = blockIdx.x * 128;
    const int tid = threadIdx.x;

    // global-load mapping: thread loads rows lkr and lkr+8 of the 16x128 tile
    const int lkr = tid >> 5;            // 0..7
    const int lc4 = (tid & 31) * 4;      // 0..124 step 4

    // compute mapping: 8x8 micro-tile with 4+4 split (conflict-free LDS.128)
    const int ty = tid >> 4, tx = tid & 15;
    const int r0 = ty * 4, r1 = 64 + ty * 4;
    const int c0 = tx * 4, c1 = 64 + tx * 4;

    const float* pA = A + m0 + lc4 + lkr * NN;
    const float* pB = B + n0 + lc4 + lkr * NN;

    // preload chunk 0
    {
        float4 a0 = *(const float4*)pA;
        float4 a1 = *(const float4*)(pA + 8 * NN);
        float4 b0 = *(const float4*)pB;
        float4 b1 = *(const float4*)(pB + 8 * NN);
        *(float4*)&As[0][lkr][lc4]     = a0;
        *(float4*)&As[0][lkr + 8][lc4] = a1;
        *(float4*)&Bs[0][lkr][lc4]     = b0;
        *(float4*)&Bs[0][lkr + 8][lc4] = b1;
    }
    __syncthreads();

    u64 acc[8][4];
    #pragma unroll
    for (int i = 0; i < 8; i++)
        #pragma unroll
        for (int j = 0; j < 4; j++) acc[i][j] = 0ull;

    const int NCH = CC / 16;   // 256 chunks
    for (int kt = 0; kt < NCH; kt++) {
        const int cur = kt & 1;
        float4 nA0, nA1, nB0, nB1;
        const bool more = (kt + 1 < NCH);
        if (more) {
            const float* qA = pA + (kt + 1) * (16 * NN);
            const float* qB = pB + (kt + 1) * (16 * NN);
            nA0 = *(const float4*)qA;  nA1 = *(const float4*)(qA + 8 * NN);
            nB0 = *(const float4*)qB;  nB1 = *(const float4*)(qB + 8 * NN);
        }
        #pragma unroll
        for (int k = 0; k < 16; k++) {
            float4 av0 = *(const float4*)&As[cur][k][r0];
            float4 av1 = *(const float4*)&As[cur][k][r1];
            ulonglong2 bv0 = *(const ulonglong2*)&Bs[cur][k][c0];
            ulonglong2 bv1 = *(const ulonglong2*)&Bs[cur][k][c1];
            u64 ap[8];
            ap[0] = pack2(av0.x, av0.x); ap[1] = pack2(av0.y, av0.y);
            ap[2] = pack2(av0.z, av0.z); ap[3] = pack2(av0.w, av0.w);
            ap[4] = pack2(av1.x, av1.x); ap[5] = pack2(av1.y, av1.y);
            ap[6] = pack2(av1.z, av1.z); ap[7] = pack2(av1.w, av1.w);
            #pragma unroll
            for (int i = 0; i < 8; i++) {
                fma2(acc[i][0], ap[i], bv0.x);
                fma2(acc[i][1], ap[i], bv0.y);
                fma2(acc[i][2], ap[i], bv1.x);
                fma2(acc[i][3], ap[i], bv1.y);
            }
        }
        if (more) {
            const int nx = cur ^ 1;
            *(float4*)&As[nx][lkr][lc4]     = nA0;
            *(float4*)&As[nx][lkr + 8][lc4] = nA1;
            *(float4*)&Bs[nx][lkr][lc4]     = nB0;
            *(float4*)&Bs[nx][lkr + 8][lc4] = nB1;
            __syncthreads();
        }
    }

    // epilogue: cos = dot / sqrt(norm_m * norm_n), mask invalid columns
    float* D = z ? d_D1 : d_D0;
    const float* normB = z ? d_normG : d_normK;
    float nb[8]; bool keep[8];
    #pragma unroll
    for (int j = 0; j < 4; j++) {
        float f0v = flag[n0 + c0 + j];
        float f1v = flag[n0 + c1 + j];
        nb[j]     = normB[n0 + c0 + j];
        nb[4 + j] = normB[n0 + c1 + j];
        keep[j]     = z ? (f0v != 0.f) : (f0v == 0.f);
        keep[4 + j] = z ? (f1v != 0.f) : (f1v == 0.f);
    }
    #pragma unroll
    for (int i = 0; i < 8; i++) {
        int gm = m0 + ((i < 4) ? (r0 + i) : (r1 + i - 4));
        float na = d_normG[gm];
        float res[8];
        #pragma unroll
        for (int j = 0; j < 4; j++) {
            float2 v = unpack2(acc[i][j]);
            int s = j * 2;
            float cA = v.x / sqrtf(na * nb[s]);
            float cB = v.y / sqrtf(na * nb[s + 1]);
            res[s]     = keep[s]     ? cA : NEGV;
            res[s + 1] = keep[s + 1] ? cB : NEGV;
        }
        float4 w0 = make_float4(res[0], res[1], res[2], res[3]);
        float4 w1 = make_float4(res[4], res[5], res[6], res[7]);
        *(float4*)&D[gm * NN + n0 + c0] = w0;
        *(float4*)&D[gm * NN + n0 + c1] = w1;
    }
}

// ---------------- kernel 3: top-2 per row (stable: ties -> lower index) --
__device__ __forceinline__ bool better(float va, int ia, float vb, int ib) {
    return (va > vb) || (va == vb && ia < ib);
}
__global__ void k_topk(const float* __restrict__ flag) {
    __shared__ float sv1[256], sv2[256];
    __shared__ int   si1[256], si2[256];
    int b = blockIdx.x;
    int z = b >> 10, row = b & 1023;
    const float* Dr = (z ? d_D1 : d_D0) + row * NN;
    int tid = threadIdx.x;

    float v1 = -3.0e38f, v2 = -3.0e38f; int i1 = -1, i2 = -1;
    #pragma unroll
    for (int j = 0; j < 4; j++) {
        int c = j * 256 + tid;
        float v = Dr[c];
        if (better(v, c, v1, i1)) { v2 = v1; i2 = i1; v1 = v; i1 = c; }
        else if (better(v, c, v2, i2)) { v2 = v; i2 = c; }
    }
    sv1[tid] = v1; si1[tid] = i1; sv2[tid] = v2; si2[tid] = i2;
    __syncthreads();
    for (int s = 128; s > 0; s >>= 1) {
        if (tid < s) {
            float w1 = sv1[tid + s], w2 = sv2[tid + s];
            int   j1 = si1[tid + s], j2 = si2[tid + s];
            float t1, t2; int ti1, ti2;
            if (better(v1, i1, w1, j1)) {
                t1 = v1; ti1 = i1;
                if (better(v2, i2, w1, j1)) { t2 = v2; ti2 = i2; }
                else                        { t2 = w1; ti2 = j1; }
            } else {
                t1 = w1; ti1 = j1;
                if (better(v1, i1, w2, j2)) { t2 = v1; ti2 = i1; }
                else                        { t2 = w2; ti2 = j2; }
            }
            v1 = t1; i1 = ti1; v2 = t2; i2 = ti2;
            sv1[tid] = v1; si1[tid] = i1; sv2[tid] = v2; si2[tid] = i2;
        }
        __syncthreads();
    }
    if (tid == 0) {
        d_topW[z][row][0] = v1; d_topW[z][row][1] = v2;
        d_topI[z][row][0] = i1; d_topI[z][row][1] = i2;
        if (flag[row] != 0.f) {
            atomicAdd(&d_meanAcc[z * 2 + 0], v1);
            atomicAdd(&d_meanAcc[z * 2 + 1], v2);
        }
    }
}

// ---------------- kernel 4: masked means -> softmax weights + dup artifact
__global__ void k_finalize(const float* __restrict__ flag) {
    __shared__ float sr[256];
    int tid = threadIdx.x;
    float s = 0.f;
    #pragma unroll
    for (int j = 0; j < 4; j++) s += flag[j * 256 + tid];
    sr[tid] = s; __syncthreads();
    for (int st = 128; st > 0; st >>= 1) {
        if (tid < st) sr[tid] += sr[tid + st];
        __syncthreads();
    }
    if (tid == 0) {
        float nm = sr[0];
        float means[4], mx = -3.0e38f;
        for (int i = 0; i < 4; i++) { means[i] = d_meanAcc[i] / nm; mx = fmaxf(mx, means[i]); }
        float e[4], Z = 0.f;
        for (int i = 0; i < 4; i++) { e[i] = expf(means[i] - mx); Z += e[i]; }
        float f0 = flag[0];
        for (int i = 0; i < 4; i++) {
            float w = e[i] / Z;
            int zz = i >> 1, jj = i & 1;
            int col0 = d_topI[zz][0][jj];
            float dup = ((f0 == 1.0f) && (col0 == 0)) ? 0.f : 1.f;
            d_wfin[i] = w;
            d_wfin[4 + i] = w * dup;
        }
    }
}

// ---------------- kernel 5: weighted gather into out[2CN..3CN) -----------
__global__ void k_rtn(const float* __restrict__ G, const float* __restrict__ K,
                      const float* __restrict__ flag, float* __restrict__ out3) {
    __shared__ float w[8];
    int n = threadIdx.x;        // 1024 threads = patch index
    if (n < 8) w[n] = d_wfin[n];
    __syncthreads();
    float fl = flag[n];
    int ia = d_topI[0][n][0], ib = d_topI[0][n][1];
    int ic = d_topI[1][n][0], idd = d_topI[1][n][1];
    int cbase = blockIdx.x * 8;
    #pragma unroll
    for (int cc = 0; cc < 8; cc++) {
        int c = cbase + cc;
        const float* Kr = K + c * NN;
        const float* Gr = G + c * NN;
        float v = 0.f;
        if (fl == 1.0f)
            v = w[0] * Kr[ia] + w[1] * Kr[ib] + w[2] * Gr[ic] + w[3] * Gr[idd];
        if (n == 0)
            v += w[4] * Kr[0] + w[5] * Kr[0] + w[6] * Gr[0] + w[7] * Gr[0];
        out3[c * NN + n] = v;
    }
}

// ---------------- launch --------------------------------------------------
extern "C" void kernel_launch(void* const* d_in, const int* in_sizes, int n_in,
                              void* d_out, int out_size) {
    (void)in_sizes; (void)n_in; (void)out_size;
    const float* G = (const float*)d_in[0];   // generated (1,4096,32,32)
    const float* K = (const float*)d_in[1];   // known
    const float* M = (const float*)d_in[2];   // mask (1,1,32,32) -> flag[1024]
    float* out = (float*)d_out;

    k_init<<<4, 256>>>();
    k_copynorm<<<dim3(4, 32), 256>>>(G, K, out);
    k_gemm<<<dim3(8, 8, 2), 256>>>(G, K, M);
    k_topk<<<2048, 256>>>(M);
    k_finalize<<<1, 256>>>(M);
    k_rtn<<<512, 1024>>>(G, K, M, out + (size_t)2 * CN);
}

// round 5
// speedup vs baseline: 1.0268x; 1.0268x over previous
#include <cuda_runtime.h>
#include <cuda_bf16.h>
#include <math.h>
#include <stdint.h>

#define CC 4096
#define NN 1024
#define CN (CC*NN)
#define KE 12288                 // expanded K = 3*CC (2-split, 3 cross products)
#define NEGV (-1e30f)

// ---------------- device scratch (no allocations allowed) ----------------
__device__ float d_D0[NN*NN];          // masked cos0 (vs known)
__device__ float d_D1[NN*NN];          // masked cos1 (vs generated)
__device__ float d_normG[NN];
__device__ float d_normK[NN];
__device__ float d_meanAcc[4];
__device__ int   d_topI[2][NN][2];
__device__ float d_wfin[8];
// expanded bf16 operands, [n][KE], packed as u32 (2 bf16)
__device__ uint32_t d_Ae [(size_t)NN*KE/2];   // G, A-pattern (b1,b1,b2)
__device__ uint32_t d_BeG[(size_t)NN*KE/2];   // G, B-pattern (b1,b2,b1)
__device__ uint32_t d_BeK[(size_t)NN*KE/2];   // K, B-pattern

// ---------------- helpers -------------------------------------------------
__device__ __forceinline__ uint32_t smem_u32(const void* p) {
    uint32_t a;
    asm("{ .reg .u64 t; cvta.to.shared.u64 t, %1; cvt.u32.u64 %0, t; }" : "=r"(a) : "l"(p));
    return a;
}
__device__ __forceinline__ unsigned short bfu(__nv_bfloat16 h) {
    unsigned short u; __builtin_memcpy(&u, &h, 2); return u;
}
__device__ __forceinline__ void cpa16(uint32_t dst, const void* src) {
    asm volatile("cp.async.cg.shared.global [%0], [%1], 16;" :: "r"(dst), "l"(src));
}
__device__ __forceinline__ void ldsm4(uint32_t* r, uint32_t addr) {
    asm volatile("ldmatrix.sync.aligned.m8n8.x4.shared.b16 {%0,%1,%2,%3}, [%4];"
                 : "=r"(r[0]), "=r"(r[1]), "=r"(r[2]), "=r"(r[3]) : "r"(addr));
}
__device__ __forceinline__ void ldsm2(uint32_t* r, uint32_t addr) {
    asm volatile("ldmatrix.sync.aligned.m8n8.x2.shared.b16 {%0,%1}, [%2];"
                 : "=r"(r[0]), "=r"(r[1]) : "r"(addr));
}
__device__ __forceinline__ void mma16816(float* c, const uint32_t* a, const uint32_t* b) {
    asm volatile("mma.sync.aligned.m16n8k16.row.col.f32.bf16.bf16.f32 "
                 "{%0,%1,%2,%3}, {%4,%5,%6,%7}, {%8,%9}, {%0,%1,%2,%3};"
                 : "+f"(c[0]), "+f"(c[1]), "+f"(c[2]), "+f"(c[3])
                 : "r"(a[0]), "r"(a[1]), "r"(a[2]), "r"(a[3]), "r"(b[0]), "r"(b[1]));
}

// ---------------- kernel 0: zero accumulators ----------------------------
__global__ void k_init() {
    int t = blockIdx.x * blockDim.x + threadIdx.x;
    if (t < NN) { d_normG[t] = 0.f; d_normK[t] = 0.f; }
    if (t < 4)  d_meanAcc[t] = 0.f;
}

// ---------------- kernel 1: copy inputs to out[0..2CN) + column norms ----
__global__ void k_copynorm(const float* __restrict__ G, const float* __restrict__ K,
                           float* __restrict__ out) {
    int n  = blockIdx.x * 256 + threadIdx.x;
    int c0 = blockIdx.y * 128;
    float sg = 0.f, sk = 0.f;
    #pragma unroll 4
    for (int i = 0; i < 128; i++) {
        int idx = (c0 + i) * NN + n;
        float g = G[idx], k = K[idx];
        out[idx]      = g;
        out[CN + idx] = k;
        sg += g * g;
        sk += k * k;
    }
    atomicAdd(&d_normG[n], sg);
    atomicAdd(&d_normK[n], sk);
}

// ---------------- kernel 1b: transpose + 2-split + K-expansion -----------
// A-pattern per original k: (b1,b1,b2); B-pattern: (b1,b2,b1).
__global__ void k_split(const float* __restrict__ G, const float* __restrict__ K) {
    __shared__ float ts[32][33];
    int z = blockIdx.z;
    const float* src = z ? K : G;
    int n0 = blockIdx.x * 32, c0 = blockIdx.y * 32;
    int tx = threadIdx.x, ty = threadIdx.y;          // 32 x 8
    #pragma unroll
    for (int i = 0; i < 4; i++) {
        int cl = ty + i * 8;
        ts[cl][tx] = src[(size_t)(c0 + cl) * NN + n0 + tx];
    }
    __syncthreads();
    int tid = ty * 32 + tx;
    int nl = tid >> 3;                 // 0..31
    int cb = (tid & 7) * 4;            // 0..28
    size_t rb = ((size_t)(n0 + nl) * KE) >> 1;   // u32 row base
    #pragma unroll
    for (int p = 0; p < 2; p++) {
        int cl = cb + p * 2;                          // even
        float v0 = ts[cl][nl], v1 = ts[cl + 1][nl];
        __nv_bfloat16 h10 = __float2bfloat16_rn(v0);
        __nv_bfloat16 h20 = __float2bfloat16_rn(v0 - __bfloat162float(h10));
        __nv_bfloat16 h11 = __float2bfloat16_rn(v1);
        __nv_bfloat16 h21 = __float2bfloat16_rn(v1 - __bfloat162float(h11));
        uint32_t b10 = bfu(h10), b20 = bfu(h20), b11 = bfu(h11), b21 = bfu(h21);
        size_t o = rb + (size_t)(3 * (c0 + cl)) / 2;  // 3*(even) -> even half idx
        // A halves: [b10,b10,b20, b11,b11,b21]
        uint32_t wa0 = b10 | (b10 << 16);
        uint32_t wa1 = b20 | (b11 << 16);
        uint32_t wa2 = b11 | (b21 << 16);
        // B halves: [b10,b20,b10, b11,b21,b11]
        uint32_t wb0 = b10 | (b20 << 16);
        uint32_t wb1 = b10 | (b11 << 16);
        uint32_t wb2 = b21 | (b11 << 16);
        if (z == 0) {
            d_Ae[o] = wa0;  d_Ae[o + 1] = wa1;  d_Ae[o + 2] = wa2;
            d_BeG[o] = wb0; d_BeG[o + 1] = wb1; d_BeG[o + 2] = wb2;
        } else {
            d_BeK[o] = wb0; d_BeK[o + 1] = wb1; d_BeK[o + 2] = wb2;
        }
    }
}

// ---------------- kernel 2: bf16 mma.sync GEMM + cos/mask epilogue -------
#define KCHUNK 64
#define NKT    (KE / KCHUNK)          // 192
#define ROWB   144                    // 64 bf16 = 128B + 16B pad (conflict-free ldmatrix)
#define TILEB  (128 * ROWB)           // 18432
#define STAGEB (2 * TILEB)            // 36864
#define NSTAGE 4
#define SMEM_GEMM (NSTAGE * STAGEB)   // 147456

__global__ __launch_bounds__(256)
void k_gemm_mma(const float* __restrict__ flag) {
    extern __shared__ char smem[];
    const uint32_t sb = smem_u32(smem);
    const int tid  = threadIdx.x;
    const int lane = tid & 31;
    const int w    = tid >> 5;
    const int WM   = (w >> 2) * 64;     // warp m-origin (2x4 warp grid)
    const int WN   = (w & 3) * 32;      // warp n-origin

    const int bx = blockIdx.x;
    const int z  = bx >> 6;
    const int m0 = ((bx >> 3) & 7) * 128;
    const int n0 = (bx & 7) * 128;

    // per-thread load mapping: row = tid/2, 4 chunks of 16B
    const int lrow = tid >> 1;
    const int lchq = (tid & 1) * 4;
    const __nv_bfloat16* gA = (const __nv_bfloat16*)d_Ae
        + (size_t)(m0 + lrow) * KE + lchq * 8;
    const __nv_bfloat16* gB = (const __nv_bfloat16*)(z ? d_BeG : d_BeK)
        + (size_t)(n0 + lrow) * KE + lchq * 8;
    const uint32_t sAofs = (uint32_t)(lrow * ROWB + lchq * 16);

    #define ISSUE(kt, s) do {                                                   \
        uint32_t _d = sb + (uint32_t)(s) * STAGEB + sAofs;                      \
        const __nv_bfloat16* _a = gA + (kt) * KCHUNK;                           \
        const __nv_bfloat16* _b = gB + (kt) * KCHUNK;                           \
        cpa16(_d,              _a);      cpa16(_d + 16,          _a + 8);       \
        cpa16(_d + 32,         _a + 16); cpa16(_d + 48,          _a + 24);      \
        cpa16(_d + TILEB,      _b);      cpa16(_d + TILEB + 16,  _b + 8);       \
        cpa16(_d + TILEB + 32, _b + 16); cpa16(_d + TILEB + 48,  _b + 24);      \
    } while (0)

    float acc[4][4][4];
    #pragma unroll
    for (int i = 0; i < 4; i++)
        #pragma unroll
        for (int j = 0; j < 4; j++)
            #pragma unroll
            for (int q = 0; q < 4; q++) acc[i][j][q] = 0.f;

    // ldmatrix lane addresses (within a stage)
    const uint32_t aOff = (uint32_t)((WM + (lane & 7) + ((lane >> 3) & 1) * 8) * ROWB
                                     + (lane >> 4) * 16);
    const uint32_t bOff = (uint32_t)((WN + (lane & 7)) * ROWB
                                     + ((lane >> 3) & 1) * 16) + TILEB;

    // prologue: 3 stages
    ISSUE(0, 0); asm volatile("cp.async.commit_group;" ::: "memory");
    ISSUE(1, 1); asm volatile("cp.async.commit_group;" ::: "memory");
    ISSUE(2, 2); asm volatile("cp.async.commit_group;" ::: "memory");

    for (int kt = 0; kt < NKT; kt++) {
        asm volatile("cp.async.wait_group 2;" ::: "memory");
        __syncthreads();
        int ip = kt + 3;
        if (ip < NKT) ISSUE(ip, ip & 3);
        asm volatile("cp.async.commit_group;" ::: "memory");

        const uint32_t stage = sb + (uint32_t)(kt & 3) * STAGEB;
        const uint32_t aA = stage + aOff;
        const uint32_t bA = stage + bOff;
        #pragma unroll
        for (int ks = 0; ks < 4; ks++) {
            uint32_t af[4][4], bf[4][2];
            #pragma unroll
            for (int i = 0; i < 4; i++) ldsm4(af[i], aA + i * (16 * ROWB) + ks * 32);
            #pragma unroll
            for (int j = 0; j < 4; j++) ldsm2(bf[j], bA + j * (8 * ROWB) + ks * 32);
            #pragma unroll
            for (int i = 0; i < 4; i++)
                #pragma unroll
                for (int j = 0; j < 4; j++)
                    mma16816(acc[i][j], af[i], bf[j]);
        }
    }
    asm volatile("cp.async.wait_group 0;" ::: "memory");
    __syncthreads();

    // epilogue: cosine + mask -> D
    float* sNa = (float*)smem;          // reuse stage memory
    float* sNb = sNa + 128;
    float* sfl = sNb + 128;
    if (tid < 128) {
        sNa[tid] = d_normG[m0 + tid];
        sNb[tid] = (z ? d_normG : d_normK)[n0 + tid];
        sfl[tid] = flag[n0 + tid];
    }
    __syncthreads();

    float* D = z ? d_D1 : d_D0;
    const int gid = lane >> 2, tig = lane & 3;
    #pragma unroll
    for (int i = 0; i < 4; i++) {
        #pragma unroll
        for (int half = 0; half < 2; half++) {
            int r = WM + i * 16 + gid + half * 8;
            float na = sNa[r];
            float* Drow = D + (size_t)(m0 + r) * NN + n0;
            #pragma unroll
            for (int j = 0; j < 4; j++) {
                int c = WN + j * 8 + tig * 2;
                float f0 = sfl[c], f1 = sfl[c + 1];
                bool k0 = z ? (f0 != 0.f) : (f0 == 0.f);
                bool k1 = z ? (f1 != 0.f) : (f1 == 0.f);
                float v0 = acc[i][j][half * 2 + 0];
                float v1 = acc[i][j][half * 2 + 1];
                float2 o;
                o.x = k0 ? (v0 / sqrtf(na * sNb[c]))     : NEGV;
                o.y = k1 ? (v1 / sqrtf(na * sNb[c + 1])) : NEGV;
                *(float2*)&Drow[c] = o;
            }
        }
    }
    #undef ISSUE
}

// ---------------- kernel 3: top-2 per row (stable ties -> lower index) ---
__device__ __forceinline__ bool better(float va, int ia, float vb, int ib) {
    return (va > vb) || (va == vb && ia < ib);
}
__global__ void k_topk(const float* __restrict__ flag) {
    __shared__ float sv1[256], sv2[256];
    __shared__ int   si1[256], si2[256];
    int b = blockIdx.x;
    int z = b >> 10, row = b & 1023;
    const float* Dr = (z ? d_D1 : d_D0) + (size_t)row * NN;
    int tid = threadIdx.x;

    float v1 = -3.0e38f, v2 = -3.0e38f; int i1 = -1, i2 = -1;
    {
        int c = tid * 4;
        float4 v = *(const float4*)&Dr[c];
        float vv[4] = {v.x, v.y, v.z, v.w};
        #pragma unroll
        for (int j = 0; j < 4; j++) {
            if (better(vv[j], c + j, v1, i1)) { v2 = v1; i2 = i1; v1 = vv[j]; i1 = c + j; }
            else if (better(vv[j], c + j, v2, i2)) { v2 = vv[j]; i2 = c + j; }
        }
    }
    sv1[tid] = v1; si1[tid] = i1; sv2[tid] = v2; si2[tid] = i2;
    __syncthreads();
    for (int s = 128; s > 0; s >>= 1) {
        if (tid < s) {
            float w1 = sv1[tid + s], w2 = sv2[tid + s];
            int   j1 = si1[tid + s], j2 = si2[tid + s];
            float t1, t2; int ti1, ti2;
            if (better(v1, i1, w1, j1)) {
                t1 = v1; ti1 = i1;
                if (better(v2, i2, w1, j1)) { t2 = v2; ti2 = i2; }
                else                        { t2 = w1; ti2 = j1; }
            } else {
                t1 = w1; ti1 = j1;
                if (better(v1, i1, w2, j2)) { t2 = v1; ti2 = i1; }
                else                        { t2 = w2; ti2 = j2; }
            }
            v1 = t1; i1 = ti1; v2 = t2; i2 = ti2;
            sv1[tid] = v1; si1[tid] = i1; sv2[tid] = v2; si2[tid] = i2;
        }
        __syncthreads();
    }
    if (tid == 0) {
        d_topI[z][row][0] = i1; d_topI[z][row][1] = i2;
        if (flag[row] != 0.f) {
            atomicAdd(&d_meanAcc[z * 2 + 0], v1);
            atomicAdd(&d_meanAcc[z * 2 + 1], v2);
        }
    }
}

// ---------------- kernel 4: softmax weights + row-0 dup artifact ---------
__global__ void k_finalize(const float* __restrict__ flag) {
    __shared__ float sr[256];
    int tid = threadIdx.x;
    float s = 0.f;
    #pragma unroll
    for (int j = 0; j < 4; j++) s += flag[j * 256 + tid];
    sr[tid] = s; __syncthreads();
    for (int st = 128; st > 0; st >>= 1) {
        if (tid < st) sr[tid] += sr[tid + st];
        __syncthreads();
    }
    if (tid == 0) {
        float nm = sr[0];
        float means[4], mx = -3.0e38f;
        for (int i = 0; i < 4; i++) { means[i] = d_meanAcc[i] / nm; mx = fmaxf(mx, means[i]); }
        float e[4], Z = 0.f;
        for (int i = 0; i < 4; i++) { e[i] = expf(means[i] - mx); Z += e[i]; }
        float f0 = flag[0];
        for (int i = 0; i < 4; i++) {
            float w = e[i] / Z;
            int zz = i >> 1, jj = i & 1;
            int col0 = d_topI[zz][0][jj];
            float dup = ((f0 == 1.0f) && (col0 == 0)) ? 0.f : 1.f;
            d_wfin[i] = w;
            d_wfin[4 + i] = w * dup;
        }
    }
}

// ---------------- kernel 5: weighted gather into out[2CN..3CN) -----------
__global__ void k_rtn(const float* __restrict__ G, const float* __restrict__ K,
                      const float* __restrict__ flag, float* __restrict__ out3) {
    __shared__ float w[8];
    int n = threadIdx.x;
    if (n < 8) w[n] = d_wfin[n];
    __syncthreads();
    float fl = flag[n];
    int ia = d_topI[0][n][0], ib = d_topI[0][n][1];
    int ic = d_topI[1][n][0], idd = d_topI[1][n][1];
    int cbase = blockIdx.x * 8;
    #pragma unroll
    for (int cc = 0; cc < 8; cc++) {
        int c = cbase + cc;
        const float* Kr = K + c * NN;
        const float* Gr = G + c * NN;
        float v = 0.f;
        if (fl == 1.0f)
            v = w[0] * Kr[ia] + w[1] * Kr[ib] + w[2] * Gr[ic] + w[3] * Gr[idd];
        if (n == 0)
            v += w[4] * Kr[0] + w[5] * Kr[0] + w[6] * Gr[0] + w[7] * Gr[0];
        out3[c * NN + n] = v;
    }
}

// ---------------- launch --------------------------------------------------
extern "C" void kernel_launch(void* const* d_in, const int* in_sizes, int n_in,
                              void* d_out, int out_size) {
    (void)in_sizes; (void)n_in; (void)out_size;
    const float* G = (const float*)d_in[0];   // generated (1,4096,32,32)
    const float* K = (const float*)d_in[1];   // known
    const float* M = (const float*)d_in[2];   // mask -> flag[1024]
    float* out = (float*)d_out;

    cudaFuncSetAttribute(k_gemm_mma, cudaFuncAttributeMaxDynamicSharedMemorySize, SMEM_GEMM);

    k_init<<<4, 256>>>();
    k_copynorm<<<dim3(4, 32), 256>>>(G, K, out);
    k_split<<<dim3(32, 128, 2), dim3(32, 8)>>>(G, K);
    k_gemm_mma<<<128, 256, SMEM_GEMM>>>(M);
    k_topk<<<2048, 256>>>(M);
    k_finalize<<<1, 256>>>(M);
    k_rtn<<<512, 1024>>>(G, K, M, out + (size_t)2 * CN);
}